// round 2
// baseline (speedup 1.0000x reference)
#include <cuda_runtime.h>
#include <cuda_bf16.h>

#define EPS 1e-5f

typedef unsigned long long u64;

// ---------------- f32x2 packed helpers (sm_103a) ----------------
__device__ __forceinline__ u64 pk2(float lo, float hi) {
    u64 r;
    asm("mov.b64 %0, {%1, %2};" : "=l"(r) : "f"(lo), "f"(hi));
    return r;
}
__device__ __forceinline__ void upk2(u64 v, float& lo, float& hi) {
    asm("mov.b64 {%0, %1}, %2;" : "=f"(lo), "=f"(hi) : "l"(v));
}
__device__ __forceinline__ u64 ffma2_(u64 a, u64 b, u64 c) {
    u64 d;
    asm("fma.rn.f32x2 %0, %1, %2, %3;" : "=l"(d) : "l"(a), "l"(b), "l"(c));
    return d;
}
__device__ __forceinline__ u64 fmul2_(u64 a, u64 b) {
    u64 d;
    asm("mul.rn.f32x2 %0, %1, %2;" : "=l"(d) : "l"(a), "l"(b));
    return d;
}

// ---------------- scratch ----------------
__device__ float  g_x_nhwc[4 * 64 * 64 * 256];   // [b][h][w][c]
__device__ int4   g_off4[4 * 9 * 64 * 64];       // per-tap clamped corner elem offsets
__device__ float4 g_cw[4 * 9 * 64 * 64];         // per-tap corner weights (0 if invalid)
__device__ float  g_pwT[256 * 256];              // [cc][o] = pw[o][cc] * bn_scale[o]
__device__ float  g_bias[256];
__device__ float  g_midT[256 * 16384];           // [c][p], p = b*4096 + h*64 + w

// ---------------- kernel 1: NCHW -> NHWC transpose ----------------
__global__ void k_transpose(const float* __restrict__ x) {
    __shared__ float tile[32][33];
    int b  = blockIdx.z;
    int s0 = blockIdx.x * 32;   // hw
    int c0 = blockIdx.y * 32;   // c
    int tx = threadIdx.x, ty = threadIdx.y;  // (32, 8)
    const float* xb = x + (size_t)b * 256 * 4096;
    float* ob = g_x_nhwc + (size_t)b * 4096 * 256;
#pragma unroll
    for (int i = 0; i < 32; i += 8)
        tile[ty + i][tx] = xb[(c0 + ty + i) * 4096 + s0 + tx];
    __syncthreads();
#pragma unroll
    for (int i = 0; i < 32; i += 8)
        ob[(s0 + ty + i) * 256 + c0 + tx] = tile[tx][ty + i];
}

// ---------------- kernel 2: weight prep ----------------
__global__ void k_prep(const float* __restrict__ pw, const float* __restrict__ bg,
                       const float* __restrict__ bb, const float* __restrict__ bm,
                       const float* __restrict__ bv) {
    int idx = blockIdx.x * 256 + threadIdx.x;   // 65536 total
    int o  = idx & 255;
    int cc = idx >> 8;
    float s = bg[o] * rsqrtf(bv[o] + EPS);
    g_pwT[cc * 256 + o] = __ldg(pw + o * 256 + cc) * s;
    if (idx < 256) {
        float s2 = bg[idx] * rsqrtf(bv[idx] + EPS);
        g_bias[idx] = bb[idx] - bm[idx] * s2;
    }
}

// ---------------- kernel 3: offset conv + sampling params ----------------
__global__ void k_offset(const float* __restrict__ gf, const float* __restrict__ offw,
                         const float* __restrict__ og, const float* __restrict__ obt,
                         const float* __restrict__ om, const float* __restrict__ ov) {
    __shared__ __align__(16) float2 s_w2[9][64][10];
    int bh = blockIdx.x;
    int b = bh >> 6, h = bh & 63;
    int w = threadIdx.x;   // 0..63

    for (int i = w; i < 9 * 64 * 9; i += 64) {
        int t = i % 9;
        int g = (i / 9) & 63;
        int k = i / 576;
        float wdy = offw[(2 * k) * 576 + g * 9 + t];
        float wdx = offw[(2 * k + 1) * 576 + g * 9 + t];
        s_w2[k][g][t] = make_float2(wdy, wdx);
    }
    __syncthreads();

    u64 acc[9];
#pragma unroll
    for (int k = 0; k < 9; k++) acc[k] = 0ull;

    const float* gfb = gf + (size_t)b * 64 * 64 * 64;
    for (int g = 0; g < 64; g++) {
        float a[9];
#pragma unroll
        for (int r = 0; r < 3; r++) {
            int hh = h + r - 1;
            bool hv = (unsigned)hh < 64u;
#pragma unroll
            for (int q = 0; q < 3; q++) {
                int ww = w + q - 1;
                bool wv2 = (unsigned)ww < 64u;
                a[r * 3 + q] = (hv && wv2) ? __ldg(gfb + (g * 64 + hh) * 64 + ww) : 0.f;
            }
        }
        u64 a2[9];
#pragma unroll
        for (int t = 0; t < 9; t++) a2[t] = pk2(a[t], a[t]);
#pragma unroll
        for (int k = 0; k < 9; k++) {
            const u64* wr = (const u64*)&s_w2[k][g][0];
            ulonglong2 w01 = *(const ulonglong2*)(wr + 0);
            ulonglong2 w23 = *(const ulonglong2*)(wr + 2);
            ulonglong2 w45 = *(const ulonglong2*)(wr + 4);
            ulonglong2 w67 = *(const ulonglong2*)(wr + 6);
            u64 w8 = wr[8];
            acc[k] = ffma2_(w01.x, a2[0], acc[k]);
            acc[k] = ffma2_(w01.y, a2[1], acc[k]);
            acc[k] = ffma2_(w23.x, a2[2], acc[k]);
            acc[k] = ffma2_(w23.y, a2[3], acc[k]);
            acc[k] = ffma2_(w45.x, a2[4], acc[k]);
            acc[k] = ffma2_(w45.y, a2[5], acc[k]);
            acc[k] = ffma2_(w67.x, a2[6], acc[k]);
            acc[k] = ffma2_(w67.y, a2[7], acc[k]);
            acc[k] = ffma2_(w8,    a2[8], acc[k]);
        }
    }

#pragma unroll
    for (int k = 0; k < 9; k++) {
        float dyr, dxr;
        upk2(acc[k], dyr, dxr);
        int j0 = 2 * k, j1 = 2 * k + 1;
        float s0 = og[j0] * rsqrtf(ov[j0] + EPS);
        float s1 = og[j1] * rsqrtf(ov[j1] + EPS);
        float dy = fmaxf((dyr - om[j0]) * s0 + obt[j0], 0.f);
        float dx = fmaxf((dxr - om[j1]) * s1 + obt[j1], 0.f);
        float ky = (float)((k / 3) - 1) * 2.0f;   // DIL = 2
        float kx = (float)((k % 3) - 1) * 2.0f;
        float gy = (float)h + ky + dy;
        float gx = (float)w + kx + dx;
        float y0f = floorf(gy), x0f = floorf(gx);
        float wy = gy - y0f, wx = gx - x0f;
        float omwy = 1.f - wy, omwx = 1.f - wx;
        int y0 = (int)y0f, x0 = (int)x0f;
        bool yv0 = (unsigned)y0 < 64u;
        bool yv1 = (unsigned)(y0 + 1) < 64u;
        bool xv0 = (unsigned)x0 < 64u;
        bool xv1 = (unsigned)(x0 + 1) < 64u;
        int y0c = min(max(y0, 0), 63);
        int y1c = min(max(y0 + 1, 0), 63);
        int x0c = min(max(x0, 0), 63);
        int x1c = min(max(x0 + 1, 0), 63);
        int idx = ((b * 9 + k) * 64 + h) * 64 + w;
        g_off4[idx] = make_int4((y0c * 64 + x0c) * 256, (y0c * 64 + x1c) * 256,
                                (y1c * 64 + x0c) * 256, (y1c * 64 + x1c) * 256);
        g_cw[idx] = make_float4(omwy * omwx * (float)(yv0 && xv0),
                                omwy * wx   * (float)(yv0 && xv1),
                                wy * omwx   * (float)(yv1 && xv0),
                                wy * wx     * (float)(yv1 && xv1));
    }
}

// ---------------- kernel 4: sample + depthwise -> g_midT ----------------
// block = 256 threads, 16 pixels of one (b,h); grid = 1024
__global__ __launch_bounds__(256) void k_sample(const float* __restrict__ dw) {
    __shared__ __align__(16) float s_mid[256][20];
    __shared__ __align__(16) int4 s_off[9][16];
    __shared__ __align__(16) u64 s_cw[9][16][4];

    int t  = blockIdx.x;
    int w0 = (t & 3) << 4;
    int h  = (t >> 2) & 63;
    int b  = t >> 8;
    int tid = threadIdx.x;

    if (tid < 144) {
        int k = tid / 16, p = tid & 15;
        int idx = ((b * 9 + k) * 64 + h) * 64 + w0 + p;
        s_off[k][p] = g_off4[idx];
        float4 cw = g_cw[idx];
        s_cw[k][p][0] = pk2(cw.x, cw.x);
        s_cw[k][p][1] = pk2(cw.y, cw.y);
        s_cw[k][p][2] = pk2(cw.z, cw.z);
        s_cw[k][p][3] = pk2(cw.w, cw.w);
    }

    int cp = tid & 127;
    int c  = cp * 2;
    int ph = tid >> 7;
    u64 dw2[9];
#pragma unroll
    for (int k = 0; k < 9; k++)
        dw2[k] = pk2(__ldg(dw + c * 9 + k), __ldg(dw + (c + 1) * 9 + k));
    __syncthreads();

    const float* xb = g_x_nhwc + (size_t)b * 4096 * 256 + c;
#pragma unroll 2
    for (int pp = 0; pp < 8; pp++) {
        int p = (ph << 3) + pp;
        u64 acc = 0ull;
#pragma unroll
        for (int k = 0; k < 9; k++) {
            int4 o4 = s_off[k][p];
            u64 v00 = __ldg((const u64*)(xb + o4.x));
            u64 v01 = __ldg((const u64*)(xb + o4.y));
            u64 v10 = __ldg((const u64*)(xb + o4.z));
            u64 v11 = __ldg((const u64*)(xb + o4.w));
            ulonglong2 cw01 = *(const ulonglong2*)&s_cw[k][p][0];
            ulonglong2 cw23 = *(const ulonglong2*)&s_cw[k][p][2];
            u64 bil = fmul2_(cw01.x, v00);
            bil = ffma2_(cw01.y, v01, bil);
            bil = ffma2_(cw23.x, v10, bil);
            bil = ffma2_(cw23.y, v11, bil);
            acc = ffma2_(dw2[k], bil, acc);
        }
        float a0, a1;
        upk2(acc, a0, a1);
        s_mid[c][p]     = a0;
        s_mid[c + 1][p] = a1;
    }
    __syncthreads();

    // store to g_midT [c][p] with p fastest
    int p0 = b * 4096 + h * 64 + w0;
    for (int i = tid; i < 4096; i += 256) {
        int row = i >> 4, col = i & 15;
        g_midT[row * 16384 + p0 + col] = s_mid[row][col];
    }
}

// ---------------- kernel 5: pointwise GEMM + BN/ReLU ----------------
// C[256 o][16384 p] = g_pwT^T x g_midT ; 128x128 tiles, 8x8 per thread
__global__ __launch_bounds__(256, 2) void k_gemm(float* __restrict__ out) {
    __shared__ __align__(16) float sW[2][8][128];
    __shared__ __align__(16) float sM[2][8][128];

    int tid = threadIdx.x;
    int tx = tid & 15;          // out dim
    int ty = tid >> 4;          // px dim
    int oblk = blockIdx.y * 128;
    int pblk = blockIdx.x * 128;

    int lr = tid >> 5;          // load row 0..7
    int lc = (tid & 31) * 4;    // load col

    const float* gW = g_pwT + lr * 256 + oblk + lc;
    const float* gM = g_midT + lr * 16384 + pblk + lc;

    u64 acc[8][4];
#pragma unroll
    for (int i = 0; i < 8; i++)
#pragma unroll
        for (int j = 0; j < 4; j++) acc[i][j] = 0ull;

    // preload stage 0
    float4 w4 = *(const float4*)gW;
    float4 m4 = *(const float4*)gM;
    *(float4*)&sW[0][lr][lc] = w4;
    *(float4*)&sM[0][lr][lc] = m4;
    __syncthreads();

#pragma unroll 1
    for (int s = 0; s < 32; s++) {
        int buf = s & 1;
        if (s + 1 < 32) {
            w4 = *(const float4*)(gW + (s + 1) * 8 * 256);
            m4 = *(const float4*)(gM + (s + 1) * 8 * 16384);
        }
#pragma unroll
        for (int k = 0; k < 8; k++) {
            float4 wa = *(const float4*)&sW[buf][k][tx * 8];
            float4 wb = *(const float4*)&sW[buf][k][tx * 8 + 4];
            const ulonglong2* mp = (const ulonglong2*)&sM[buf][k][ty * 8];
            ulonglong2 m01 = mp[0];
            ulonglong2 m23 = mp[1];
            u64 w2[8];
            w2[0] = pk2(wa.x, wa.x); w2[1] = pk2(wa.y, wa.y);
            w2[2] = pk2(wa.z, wa.z); w2[3] = pk2(wa.w, wa.w);
            w2[4] = pk2(wb.x, wb.x); w2[5] = pk2(wb.y, wb.y);
            w2[6] = pk2(wb.z, wb.z); w2[7] = pk2(wb.w, wb.w);
#pragma unroll
            for (int i = 0; i < 8; i++) {
                acc[i][0] = ffma2_(w2[i], m01.x, acc[i][0]);
                acc[i][1] = ffma2_(w2[i], m01.y, acc[i][1]);
                acc[i][2] = ffma2_(w2[i], m23.x, acc[i][2]);
                acc[i][3] = ffma2_(w2[i], m23.y, acc[i][3]);
            }
        }
        if (s + 1 < 32) {
            *(float4*)&sW[buf ^ 1][lr][lc] = w4;
            *(float4*)&sM[buf ^ 1][lr][lc] = m4;
        }
        __syncthreads();
    }

    // epilogue: bias + relu, store
    int b  = pblk >> 12;
    int hw = (pblk & 4095) + ty * 8;
    float* ob = out + (size_t)b * 256 * 4096 + hw;
#pragma unroll
    for (int i = 0; i < 8; i++) {
        int o = oblk + tx * 8 + i;
        float bias = g_bias[o];
        float* orow = ob + o * 4096;
#pragma unroll
        for (int j = 0; j < 4; j++) {
            float lo, hi;
            upk2(acc[i][j], lo, hi);
            float2 v = make_float2(fmaxf(lo + bias, 0.f), fmaxf(hi + bias, 0.f));
            *(float2*)(orow + j * 2) = v;
        }
    }
}

// ---------------- launch ----------------
extern "C" void kernel_launch(void* const* d_in, const int* in_sizes, int n_in,
                              void* d_out, int out_size) {
    const float* x    = (const float*)d_in[0];
    const float* gf   = (const float*)d_in[1];
    const float* offw = (const float*)d_in[2];
    const float* og   = (const float*)d_in[3];
    const float* obt  = (const float*)d_in[4];
    const float* om   = (const float*)d_in[5];
    const float* ov   = (const float*)d_in[6];
    const float* dww  = (const float*)d_in[7];
    const float* pww  = (const float*)d_in[8];
    const float* bg   = (const float*)d_in[9];
    const float* bb   = (const float*)d_in[10];
    const float* bm   = (const float*)d_in[11];
    const float* bv   = (const float*)d_in[12];
    float* out = (float*)d_out;

    k_transpose<<<dim3(128, 8, 4), dim3(32, 8)>>>(x);
    k_prep<<<256, 256>>>(pww, bg, bb, bm, bv);
    k_offset<<<256, 64>>>(gf, offw, og, obt, om, ov);
    k_sample<<<1024, 256>>>(dww);
    k_gemm<<<dim3(128, 2), 256>>>(out);
}

// round 3
// speedup vs baseline: 1.1018x; 1.1018x over previous
#include <cuda_runtime.h>
#include <cuda_bf16.h>

#define EPS 1e-5f

typedef unsigned long long u64;

// ---------------- f32x2 packed helpers (sm_103a) ----------------
__device__ __forceinline__ u64 pk2(float lo, float hi) {
    u64 r;
    asm("mov.b64 %0, {%1, %2};" : "=l"(r) : "f"(lo), "f"(hi));
    return r;
}
__device__ __forceinline__ void upk2(u64 v, float& lo, float& hi) {
    asm("mov.b64 {%0, %1}, %2;" : "=f"(lo), "=f"(hi) : "l"(v));
}
__device__ __forceinline__ u64 ffma2_(u64 a, u64 b, u64 c) {
    u64 d;
    asm("fma.rn.f32x2 %0, %1, %2, %3;" : "=l"(d) : "l"(a), "l"(b), "l"(c));
    return d;
}
__device__ __forceinline__ u64 fmul2_(u64 a, u64 b) {
    u64 d;
    asm("mul.rn.f32x2 %0, %1, %2;" : "=l"(d) : "l"(a), "l"(b));
    return d;
}

// ---------------- scratch ----------------
__device__ float  g_x_nhwc[4 * 64 * 64 * 256];   // [b][h][w][c]
__device__ int4   g_off4[4 * 9 * 64 * 64];       // clamped corner elem offsets
__device__ float4 g_cw[4 * 9 * 64 * 64];         // corner weights (0 if invalid)
__device__ float  g_pwT[256 * 256];              // [c][o] = pw[o][c] * bn_scale[o]
__device__ float  g_bias[256];
__device__ float  g_midT[256 * 16384];           // [c][p], p = b*4096 + h*64 + w

// ---------------- kernel 1: NCHW -> NHWC transpose ----------------
__global__ void k_transpose(const float* __restrict__ x) {
    __shared__ float tile[32][33];
    int b  = blockIdx.z;
    int s0 = blockIdx.x * 32;
    int c0 = blockIdx.y * 32;
    int tx = threadIdx.x, ty = threadIdx.y;  // (32, 8)
    const float* xb = x + (size_t)b * 256 * 4096;
    float* ob = g_x_nhwc + (size_t)b * 4096 * 256;
#pragma unroll
    for (int i = 0; i < 32; i += 8)
        tile[ty + i][tx] = xb[(c0 + ty + i) * 4096 + s0 + tx];
    __syncthreads();
#pragma unroll
    for (int i = 0; i < 32; i += 8)
        ob[(s0 + ty + i) * 256 + c0 + tx] = tile[tx][ty + i];
}

// ---------------- kernel 2: weight prep ----------------
__global__ void k_prep(const float* __restrict__ pw, const float* __restrict__ bg,
                       const float* __restrict__ bb, const float* __restrict__ bm,
                       const float* __restrict__ bv) {
    int idx = blockIdx.x * 256 + threadIdx.x;   // 65536 total
    int o  = idx & 255;
    int cc = idx >> 8;
    float s = bg[o] * rsqrtf(bv[o] + EPS);
    g_pwT[cc * 256 + o] = __ldg(pw + o * 256 + cc) * s;
    if (idx < 256) {
        float s2 = bg[idx] * rsqrtf(bv[idx] + EPS);
        g_bias[idx] = bb[idx] - bm[idx] * s2;
    }
}

// ---------------- kernel 3: offset conv + sampling params ----------------
__global__ void k_offset(const float* __restrict__ gf, const float* __restrict__ offw,
                         const float* __restrict__ og, const float* __restrict__ obt,
                         const float* __restrict__ om, const float* __restrict__ ov) {
    __shared__ __align__(16) float2 s_w2[9][64][10];
    int bh = blockIdx.x;
    int b = bh >> 6, h = bh & 63;
    int w = threadIdx.x;   // 0..63

    for (int i = w; i < 9 * 64 * 9; i += 64) {
        int t = i % 9;
        int g = (i / 9) & 63;
        int k = i / 576;
        float wdy = offw[(2 * k) * 576 + g * 9 + t];
        float wdx = offw[(2 * k + 1) * 576 + g * 9 + t];
        s_w2[k][g][t] = make_float2(wdy, wdx);
    }
    __syncthreads();

    u64 acc[9];
#pragma unroll
    for (int k = 0; k < 9; k++) acc[k] = 0ull;

    const float* gfb = gf + (size_t)b * 64 * 64 * 64;
    for (int g = 0; g < 64; g++) {
        float a[9];
#pragma unroll
        for (int r = 0; r < 3; r++) {
            int hh = h + r - 1;
            bool hv = (unsigned)hh < 64u;
#pragma unroll
            for (int q = 0; q < 3; q++) {
                int ww = w + q - 1;
                bool wv2 = (unsigned)ww < 64u;
                a[r * 3 + q] = (hv && wv2) ? __ldg(gfb + (g * 64 + hh) * 64 + ww) : 0.f;
            }
        }
        u64 a2[9];
#pragma unroll
        for (int t = 0; t < 9; t++) a2[t] = pk2(a[t], a[t]);
#pragma unroll
        for (int k = 0; k < 9; k++) {
            const u64* wr = (const u64*)&s_w2[k][g][0];
            ulonglong2 w01 = *(const ulonglong2*)(wr + 0);
            ulonglong2 w23 = *(const ulonglong2*)(wr + 2);
            ulonglong2 w45 = *(const ulonglong2*)(wr + 4);
            ulonglong2 w67 = *(const ulonglong2*)(wr + 6);
            u64 w8 = wr[8];
            acc[k] = ffma2_(w01.x, a2[0], acc[k]);
            acc[k] = ffma2_(w01.y, a2[1], acc[k]);
            acc[k] = ffma2_(w23.x, a2[2], acc[k]);
            acc[k] = ffma2_(w23.y, a2[3], acc[k]);
            acc[k] = ffma2_(w45.x, a2[4], acc[k]);
            acc[k] = ffma2_(w45.y, a2[5], acc[k]);
            acc[k] = ffma2_(w67.x, a2[6], acc[k]);
            acc[k] = ffma2_(w67.y, a2[7], acc[k]);
            acc[k] = ffma2_(w8,    a2[8], acc[k]);
        }
    }

#pragma unroll
    for (int k = 0; k < 9; k++) {
        float dyr, dxr;
        upk2(acc[k], dyr, dxr);
        int j0 = 2 * k, j1 = 2 * k + 1;
        float s0 = og[j0] * rsqrtf(ov[j0] + EPS);
        float s1 = og[j1] * rsqrtf(ov[j1] + EPS);
        float dy = fmaxf((dyr - om[j0]) * s0 + obt[j0], 0.f);
        float dx = fmaxf((dxr - om[j1]) * s1 + obt[j1], 0.f);
        float ky = (float)((k / 3) - 1) * 2.0f;   // DIL = 2
        float kx = (float)((k % 3) - 1) * 2.0f;
        float gy = (float)h + ky + dy;
        float gx = (float)w + kx + dx;
        float y0f = floorf(gy), x0f = floorf(gx);
        float wy = gy - y0f, wx = gx - x0f;
        float omwy = 1.f - wy, omwx = 1.f - wx;
        int y0 = (int)y0f, x0 = (int)x0f;
        bool yv0 = (unsigned)y0 < 64u;
        bool yv1 = (unsigned)(y0 + 1) < 64u;
        bool xv0 = (unsigned)x0 < 64u;
        bool xv1 = (unsigned)(x0 + 1) < 64u;
        int y0c = min(max(y0, 0), 63);
        int y1c = min(max(y0 + 1, 0), 63);
        int x0c = min(max(x0, 0), 63);
        int x1c = min(max(x0 + 1, 0), 63);
        int idx = ((b * 9 + k) * 64 + h) * 64 + w;
        g_off4[idx] = make_int4((y0c * 64 + x0c) * 256, (y0c * 64 + x1c) * 256,
                                (y1c * 64 + x0c) * 256, (y1c * 64 + x1c) * 256);
        g_cw[idx] = make_float4(omwy * omwx * (float)(yv0 && xv0),
                                omwy * wx   * (float)(yv0 && xv1),
                                wy * omwx   * (float)(yv1 && xv0),
                                wy * wx     * (float)(yv1 && xv1));
    }
}

// ---------------- kernel 4: sample + depthwise -> g_midT ----------------
// block = 256 threads; 16 px of one (b,h); thread = (cg 0..63 -> 4 channels, ps 0..3 -> 4 px)
__global__ __launch_bounds__(256) void k_sample(const float* __restrict__ dw) {
    __shared__ float s_mid[16][264];                 // [p][c], padded
    __shared__ __align__(16) int4 s_off[9][16];
    __shared__ __align__(16) u64 s_cw[9][16][4];

    int t  = blockIdx.x;
    int w0 = (t & 3) << 4;
    int h  = (t >> 2) & 63;
    int b  = t >> 8;
    int tid = threadIdx.x;

    if (tid < 144) {
        int k = tid / 16, p = tid & 15;
        int idx = ((b * 9 + k) * 64 + h) * 64 + w0 + p;
        s_off[k][p] = g_off4[idx];
        float4 cw = g_cw[idx];
        s_cw[k][p][0] = pk2(cw.x, cw.x);
        s_cw[k][p][1] = pk2(cw.y, cw.y);
        s_cw[k][p][2] = pk2(cw.z, cw.z);
        s_cw[k][p][3] = pk2(cw.w, cw.w);
    }

    int cg = tid & 63;
    int c  = cg * 4;
    int ps = tid >> 6;

    u64 dwv[9][2];
#pragma unroll
    for (int k = 0; k < 9; k++) {
        dwv[k][0] = pk2(__ldg(dw + c * 9 + k),       __ldg(dw + (c + 1) * 9 + k));
        dwv[k][1] = pk2(__ldg(dw + (c + 2) * 9 + k), __ldg(dw + (c + 3) * 9 + k));
    }
    __syncthreads();

    const float* xb = g_x_nhwc + (size_t)b * 4096 * 256 + c;
#pragma unroll 2
    for (int i = 0; i < 4; i++) {
        int p = ps * 4 + i;
        u64 a0 = 0ull, a1 = 0ull;
#pragma unroll
        for (int k = 0; k < 9; k++) {
            int4 o4 = s_off[k][p];
            float4 v00 = __ldg((const float4*)(xb + o4.x));
            float4 v01 = __ldg((const float4*)(xb + o4.y));
            float4 v10 = __ldg((const float4*)(xb + o4.z));
            float4 v11 = __ldg((const float4*)(xb + o4.w));
            ulonglong2 c01 = *(const ulonglong2*)&s_cw[k][p][0];
            ulonglong2 c23 = *(const ulonglong2*)&s_cw[k][p][2];
            const u64* q00 = (const u64*)&v00;
            const u64* q01 = (const u64*)&v01;
            const u64* q10 = (const u64*)&v10;
            const u64* q11 = (const u64*)&v11;
            u64 b0 = fmul2_(c01.x, q00[0]);
            u64 b1 = fmul2_(c01.x, q00[1]);
            b0 = ffma2_(c01.y, q01[0], b0);
            b1 = ffma2_(c01.y, q01[1], b1);
            b0 = ffma2_(c23.x, q10[0], b0);
            b1 = ffma2_(c23.x, q10[1], b1);
            b0 = ffma2_(c23.y, q11[0], b0);
            b1 = ffma2_(c23.y, q11[1], b1);
            a0 = ffma2_(dwv[k][0], b0, a0);
            a1 = ffma2_(dwv[k][1], b1, a1);
        }
        float f0, f1, f2, f3;
        upk2(a0, f0, f1);
        upk2(a1, f2, f3);
        *(float4*)&s_mid[p][c] = make_float4(f0, f1, f2, f3);
    }
    __syncthreads();

    int p0 = b * 4096 + h * 64 + w0;
    for (int i2 = tid; i2 < 4096; i2 += 256) {
        int cc = i2 >> 4, pp = i2 & 15;
        g_midT[cc * 16384 + p0 + pp] = s_mid[pp][cc];
    }
}

// ---------------- kernel 5: pointwise GEMM + BN/ReLU ----------------
// C[256 o][16384 px]; block tile 64o x 256px; 256 threads; thread 8o x 8px.
// Warp spans px only -> W reads are smem broadcasts (pre-duplicated u64 pairs).
__global__ __launch_bounds__(256, 2) void k_gemm(float* __restrict__ out) {
    __shared__ __align__(16) u64  sW[2][8][64];     // (w,w) duplicated pairs
    __shared__ __align__(16) float sM[2][8][256];

    int tid  = threadIdx.x;
    int og   = tid >> 5;            // 0..7: owns o = oblk + og*8 .. +7
    int lane = tid & 31;
    int pxA  = lane * 4;            // px 0..127
    int pxB  = 128 + lane * 4;      // px 128..255
    int oblk = blockIdx.y * 64;
    int pblk = blockIdx.x * 256;

    int kr = tid >> 5;              // loader row 0..7
    int oc = lane * 2;
    int pc = lane * 8;
    const float* gW = g_pwT + kr * 256 + oblk + oc;
    const float* gM = g_midT + (size_t)kr * 16384 + pblk + pc;

    u64 acc[8][4];
#pragma unroll
    for (int o = 0; o < 8; o++)
#pragma unroll
        for (int j = 0; j < 4; j++) acc[o][j] = 0ull;

    float2 wv = *(const float2*)gW;
    float4 mva = *(const float4*)gM;
    float4 mvb = *(const float4*)(gM + 4);
    {
        ulonglong2 wd;
        wd.x = pk2(wv.x, wv.x);
        wd.y = pk2(wv.y, wv.y);
        *(ulonglong2*)&sW[0][kr][oc] = wd;
        *(float4*)&sM[0][kr][pc] = mva;
        *(float4*)&sM[0][kr][pc + 4] = mvb;
    }
    __syncthreads();

#pragma unroll 1
    for (int s = 0; s < 32; s++) {
        int buf = s & 1;
        if (s < 31) {
            wv  = *(const float2*)(gW + (s + 1) * 8 * 256);
            mva = *(const float4*)(gM + (size_t)(s + 1) * 8 * 16384);
            mvb = *(const float4*)(gM + (size_t)(s + 1) * 8 * 16384 + 4);
        }
#pragma unroll
        for (int k = 0; k < 8; k++) {
            const ulonglong2* wp = (const ulonglong2*)&sW[buf][k][og * 8];
            ulonglong2 w01 = wp[0];
            ulonglong2 w23 = wp[1];
            ulonglong2 w45 = wp[2];
            ulonglong2 w67 = wp[3];
            ulonglong2 mA = *(const ulonglong2*)&sM[buf][k][pxA];
            ulonglong2 mB = *(const ulonglong2*)&sM[buf][k][pxB];
            u64 w_[8] = {w01.x, w01.y, w23.x, w23.y, w45.x, w45.y, w67.x, w67.y};
#pragma unroll
            for (int o = 0; o < 8; o++) {
                acc[o][0] = ffma2_(w_[o], mA.x, acc[o][0]);
                acc[o][1] = ffma2_(w_[o], mA.y, acc[o][1]);
                acc[o][2] = ffma2_(w_[o], mB.x, acc[o][2]);
                acc[o][3] = ffma2_(w_[o], mB.y, acc[o][3]);
            }
        }
        if (s < 31) {
            ulonglong2 wd;
            wd.x = pk2(wv.x, wv.x);
            wd.y = pk2(wv.y, wv.y);
            *(ulonglong2*)&sW[buf ^ 1][kr][oc] = wd;
            *(float4*)&sM[buf ^ 1][kr][pc] = mva;
            *(float4*)&sM[buf ^ 1][kr][pc + 4] = mvb;
        }
        __syncthreads();
    }

    int b  = pblk >> 12;
    int hw = pblk & 4095;
    float* ob = out + (size_t)b * 256 * 4096 + hw;
#pragma unroll
    for (int o = 0; o < 8; o++) {
        int oo = oblk + og * 8 + o;
        float bias = __ldg(g_bias + oo);
        float l0, h0, l1, h1;
        float4 r;
        upk2(acc[o][0], l0, h0);
        upk2(acc[o][1], l1, h1);
        r.x = fmaxf(l0 + bias, 0.f);
        r.y = fmaxf(h0 + bias, 0.f);
        r.z = fmaxf(l1 + bias, 0.f);
        r.w = fmaxf(h1 + bias, 0.f);
        *(float4*)(ob + (size_t)oo * 4096 + pxA) = r;
        upk2(acc[o][2], l0, h0);
        upk2(acc[o][3], l1, h1);
        r.x = fmaxf(l0 + bias, 0.f);
        r.y = fmaxf(h0 + bias, 0.f);
        r.z = fmaxf(l1 + bias, 0.f);
        r.w = fmaxf(h1 + bias, 0.f);
        *(float4*)(ob + (size_t)oo * 4096 + pxB) = r;
    }
}

// ---------------- launch ----------------
extern "C" void kernel_launch(void* const* d_in, const int* in_sizes, int n_in,
                              void* d_out, int out_size) {
    const float* x    = (const float*)d_in[0];
    const float* gf   = (const float*)d_in[1];
    const float* offw = (const float*)d_in[2];
    const float* og   = (const float*)d_in[3];
    const float* obt  = (const float*)d_in[4];
    const float* om   = (const float*)d_in[5];
    const float* ov   = (const float*)d_in[6];
    const float* dww  = (const float*)d_in[7];
    const float* pww  = (const float*)d_in[8];
    const float* bg   = (const float*)d_in[9];
    const float* bb   = (const float*)d_in[10];
    const float* bm   = (const float*)d_in[11];
    const float* bv   = (const float*)d_in[12];
    float* out = (float*)d_out;

    k_transpose<<<dim3(128, 8, 4), dim3(32, 8)>>>(x);
    k_prep<<<256, 256>>>(pww, bg, bb, bm, bv);
    k_offset<<<256, 64>>>(gf, offw, og, obt, om, ov);
    k_sample<<<1024, 256>>>(dww);
    k_gemm<<<dim3(64, 4), 256>>>(out);
}